// round 16
// baseline (speedup 1.0000x reference)
#include <cuda_runtime.h>
#include <cuda_bf16.h>
#include <cuda_fp16.h>
#include <cstdint>
#include <math.h>

#define D 128
#define HD 256

static const int NMAX = 100000;
static const int EMAX = 1600000;

// ---------------------------------------------------------------------------
// Scratch. xl/xr stored as fp16 head-major planes [2][N][128].
// ---------------------------------------------------------------------------
__device__ __nv_bfloat16 g_hh[(size_t)NMAX * D];
__device__ __nv_bfloat16 g_hl[(size_t)NMAX * D];
__device__ __half g_xl [(size_t)2 * NMAX * D];
__device__ __half g_xr [(size_t)2 * NMAX * D];
__device__ __nv_bfloat16 g_wlh[HD * D];
__device__ __nv_bfloat16 g_wll[HD * D];
__device__ __nv_bfloat16 g_wrh[HD * D];
__device__ __nv_bfloat16 g_wrl[HD * D];
__device__ __nv_bfloat16 g_wsh[D * D];
__device__ __nv_bfloat16 g_wsl[D * D];
__device__ int   g_deg [NMAX];
__device__ int   g_off [NMAX];
__device__ int   g_pos [NMAX];
__device__ int   g_bsum[128];
__device__ int   g_srcs[EMAX];

// ---------------------------------------------------------------------------
// PTX helpers
// ---------------------------------------------------------------------------
__device__ __forceinline__ unsigned s2u(const void* p) {
  unsigned a;
  asm("{ .reg .u64 t; cvta.to.shared.u64 t, %1; cvt.u32.u64 %0, t; }"
      : "=r"(a) : "l"(p));
  return a;
}

__device__ __forceinline__ void ldm4(unsigned* r, unsigned addr) {
  asm volatile("ldmatrix.sync.aligned.m8n8.x4.shared.b16 {%0,%1,%2,%3}, [%4];"
               : "=r"(r[0]), "=r"(r[1]), "=r"(r[2]), "=r"(r[3]) : "r"(addr));
}

__device__ __forceinline__ void mma_bf16(float* c, const unsigned* a,
                                         const unsigned* b) {
  asm volatile(
      "mma.sync.aligned.m16n8k16.row.col.f32.bf16.bf16.f32 "
      "{%0,%1,%2,%3}, {%4,%5,%6,%7}, {%8,%9}, {%0,%1,%2,%3};"
      : "+f"(c[0]), "+f"(c[1]), "+f"(c[2]), "+f"(c[3])
      : "r"(a[0]), "r"(a[1]), "r"(a[2]), "r"(a[3]), "r"(b[0]), "r"(b[1]));
}

__device__ __forceinline__ void cpa16(unsigned daddr, const void* g) {
  asm volatile("cp.async.cg.shared.global [%0], [%1], 16;"
               :: "r"(daddr), "l"(g));
}
#define CP_COMMIT() asm volatile("cp.async.commit_group;" ::: "memory")
#define CP_WAIT0()  asm volatile("cp.async.wait_group 0;" ::: "memory")

__device__ __forceinline__ uint2 pack_hi_lo(float4 v, uint2& lo) {
  __nv_bfloat162 h0 = __floats2bfloat162_rn(v.x, v.y);
  __nv_bfloat162 h1 = __floats2bfloat162_rn(v.z, v.w);
  float4 r;
  r.x = v.x - __bfloat162float(h0.x);
  r.y = v.y - __bfloat162float(h0.y);
  r.z = v.z - __bfloat162float(h1.x);
  r.w = v.w - __bfloat162float(h1.y);
  __nv_bfloat162 l0 = __floats2bfloat162_rn(r.x, r.y);
  __nv_bfloat162 l1 = __floats2bfloat162_rn(r.z, r.w);
  uint2 hi;
  hi.x = *(unsigned*)&h0;
  hi.y = *(unsigned*)&h1;
  lo.x = *(unsigned*)&l0;
  lo.y = *(unsigned*)&l1;
  return hi;
}

__device__ __forceinline__ float4 half4_to_float4(uint2 p) {
  float2 f01 = __half22float2(*(__half2*)&p.x);
  float2 f23 = __half22float2(*(__half2*)&p.y);
  float4 r;
  r.x = f01.x; r.y = f01.y; r.z = f23.x; r.w = f23.y;
  return r;
}

// ---------------------------------------------------------------------------
// LayerNorm + ReLU + bf16 split (warp per row)
// ---------------------------------------------------------------------------
__global__ void ln_relu_kernel(const float* __restrict__ x,
                               const float* __restrict__ gamma,
                               const float* __restrict__ beta, int n) {
  int gtid = blockIdx.x * blockDim.x + threadIdx.x;
  int row = gtid >> 5;
  int lane = gtid & 31;
  if (row >= n) return;

  float4 v = *(const float4*)(x + (size_t)row * D + lane * 4);
  float s = v.x + v.y + v.z + v.w;
#pragma unroll
  for (int o = 16; o; o >>= 1) s += __shfl_xor_sync(0xffffffffu, s, o);
  float mu = s * (1.f / 128.f);
  float dx = v.x - mu, dy = v.y - mu, dz = v.z - mu, dw = v.w - mu;
  float q = dx * dx + dy * dy + dz * dz + dw * dw;
#pragma unroll
  for (int o = 16; o; o >>= 1) q += __shfl_xor_sync(0xffffffffu, q, o);
  float rstd = rsqrtf(q * (1.f / 128.f) + 1e-5f);

  float4 g = *(const float4*)(gamma + lane * 4);
  float4 b = *(const float4*)(beta + lane * 4);
  float4 h;
  h.x = fmaxf(fmaf(dx * rstd, g.x, b.x), 0.f);
  h.y = fmaxf(fmaf(dy * rstd, g.y, b.y), 0.f);
  h.z = fmaxf(fmaf(dz * rstd, g.z, b.z), 0.f);
  h.w = fmaxf(fmaf(dw * rstd, g.w, b.w), 0.f);
  uint2 lo;
  uint2 hi = pack_hi_lo(h, lo);
  *(uint2*)(g_hh + (size_t)row * D + lane * 4) = hi;
  *(uint2*)(g_hl + (size_t)row * D + lane * 4) = lo;
}

// ---------------------------------------------------------------------------
// Merged weight transpose + bf16 split (Wl, Wr, resW in one launch)
// ---------------------------------------------------------------------------
__global__ void split_all_kernel(const float* __restrict__ Wl,
                                 const float* __restrict__ Wr,
                                 const float* __restrict__ Ws) {
  int i = blockIdx.x * blockDim.x + threadIdx.x;
  if (i >= 81920) return;
  const float* W;
  __nv_bfloat16 *oh, *ol;
  int rem, Ncols;
  if (i < 32768) {
    W = Wl; oh = g_wlh; ol = g_wll; rem = i; Ncols = HD;
  } else if (i < 65536) {
    W = Wr; oh = g_wrh; ol = g_wrl; rem = i - 32768; Ncols = HD;
  } else {
    W = Ws; oh = g_wsh; ol = g_wsl; rem = i - 65536; Ncols = D;
  }
  int nrow = rem >> 7;
  int k = rem & 127;
  float v = W[(size_t)k * Ncols + nrow];
  __nv_bfloat16 h = __float2bfloat16(v);
  __nv_bfloat16 l = __float2bfloat16(v - __bfloat162float(h));
  oh[rem] = h;
  ol[rem] = l;
}

// ---------------------------------------------------------------------------
// CSR build (independent side chain): zero -> hist -> scan -> scatter
// ---------------------------------------------------------------------------
__global__ void zero_deg_kernel(int n) {
  int i = blockIdx.x * blockDim.x + threadIdx.x;
  if (i < n) g_deg[i] = 0;
}

__global__ void hist_kernel(const int* __restrict__ ei, int e) {
  int i = blockIdx.x * blockDim.x + threadIdx.x;
  if (i < e) atomicAdd(&g_deg[ei[e + i]], 1);
}

__global__ __launch_bounds__(1024) void scan1_kernel(int n) {
  __shared__ int sh[1024];
  int i = blockIdx.x * 1024 + threadIdx.x;
  int v = (i < n) ? g_deg[i] : 0;
  sh[threadIdx.x] = v;
  __syncthreads();
#pragma unroll
  for (int o = 1; o < 1024; o <<= 1) {
    int t = (threadIdx.x >= o) ? sh[threadIdx.x - o] : 0;
    __syncthreads();
    sh[threadIdx.x] += t;
    __syncthreads();
  }
  int incl = sh[threadIdx.x];
  if (i < n) g_off[i] = incl - v;
  if (threadIdx.x == 1023) g_bsum[blockIdx.x] = incl;
}

__global__ void scan2_kernel(int nb) {
  __shared__ int sh[128];
  int i = threadIdx.x;
  int v = (i < nb) ? g_bsum[i] : 0;
  sh[i] = v;
  __syncthreads();
#pragma unroll
  for (int o = 1; o < 128; o <<= 1) {
    int t = (i >= o) ? sh[i - o] : 0;
    __syncthreads();
    sh[i] += t;
    __syncthreads();
  }
  if (i < nb) g_bsum[i] = sh[i] - v;
}

__global__ void scan3_kernel(int n) {
  int i = blockIdx.x * blockDim.x + threadIdx.x;
  if (i < n) {
    int o = g_off[i] + g_bsum[i >> 10];
    g_off[i] = o;
    g_pos[i] = o;
  }
}

__global__ void scatter_kernel(const int* __restrict__ ei, int e) {
  int i = blockIdx.x * blockDim.x + threadIdx.x;
  if (i < e) {
    int dst = ei[e + i];
    int p = atomicAdd(&g_pos[dst], 1);
    g_srcs[p] = ei[i];
  }
}

// ---------------------------------------------------------------------------
// MERGED bf16x3 GEMM: blockIdx.x 0-3 -> xl, 4-7 -> xr, 8-9 -> out.
// ---------------------------------------------------------------------------
#define BPAD 72
#define OFF_AH 0
#define OFF_AL (128 * BPAD)
#define OFF_BH (256 * BPAD)
#define OFF_BL (320 * BPAD)
#define BUF_HALVES (384 * BPAD)
#define SM_TOTAL (2 * BUF_HALVES * 2)

__device__ __forceinline__ void gemm_load(unsigned sbase, int buf,
                                          int kc, int rowBase, int colBase,
                                          const __nv_bfloat16* Bh,
                                          const __nv_bfloat16* Bl,
                                          int M, int tid) {
  unsigned base = sbase + buf * BUF_HALVES * 2;
  for (int idx = tid; idx < 1024; idx += 256) {
    int row = idx >> 3, c = idx & 7;
    int rg = min(rowBase + row, M - 1);
    unsigned so = (row * BPAD + c * 8) * 2;
    cpa16(base + OFF_AH * 2 + so, g_hh + (size_t)rg * D + kc + c * 8);
    cpa16(base + OFF_AL * 2 + so, g_hl + (size_t)rg * D + kc + c * 8);
  }
  for (int idx = tid; idx < 512; idx += 256) {
    int row = idx >> 3, c = idx & 7;
    unsigned so = (row * BPAD + c * 8) * 2;
    cpa16(base + OFF_BH * 2 + so, Bh + (size_t)(colBase + row) * D + kc + c * 8);
    cpa16(base + OFF_BL * 2 + so, Bl + (size_t)(colBase + row) * D + kc + c * 8);
  }
}

__device__ __forceinline__ void gemm_compute(unsigned sbase, int buf, int lane,
                                             int wm, int wn,
                                             float acc[2][4][4]) {
  unsigned base = sbase + buf * BUF_HALVES * 2;
#pragma unroll
  for (int ks = 0; ks < 4; ks++) {
    unsigned aH[2][4], aL[2][4], bH[2][4], bL[2][4];
    unsigned aoff = ((wm + (lane & 15)) * BPAD + ks * 16 + (lane >> 4) * 8) * 2;
    unsigned boff = ((wn + (lane & 7) + ((lane >> 4) << 3)) * BPAD +
                     ks * 16 + (((lane >> 3) & 1) << 3)) * 2;
#pragma unroll
    for (int mt = 0; mt < 2; mt++) {
      ldm4(aH[mt], base + OFF_AH * 2 + aoff + mt * (16 * BPAD * 2));
      ldm4(aL[mt], base + OFF_AL * 2 + aoff + mt * (16 * BPAD * 2));
    }
#pragma unroll
    for (int j = 0; j < 2; j++) {
      ldm4(bH[j], base + OFF_BH * 2 + boff + j * (16 * BPAD * 2));
      ldm4(bL[j], base + OFF_BL * 2 + boff + j * (16 * BPAD * 2));
    }
#pragma unroll
    for (int mt = 0; mt < 2; mt++)
#pragma unroll
      for (int j = 0; j < 2; j++) {
        mma_bf16(acc[mt][2 * j + 0], aH[mt], &bH[j][0]);
        mma_bf16(acc[mt][2 * j + 1], aH[mt], &bH[j][2]);
        mma_bf16(acc[mt][2 * j + 0], aH[mt], &bL[j][0]);
        mma_bf16(acc[mt][2 * j + 1], aH[mt], &bL[j][2]);
        mma_bf16(acc[mt][2 * j + 0], aL[mt], &bH[j][0]);
        mma_bf16(acc[mt][2 * j + 1], aL[mt], &bH[j][2]);
      }
  }
}

__global__ __launch_bounds__(256, 2)
void hmma_gemm_all_kernel(const float* __restrict__ bl,
                          const float* __restrict__ br,
                          const float* __restrict__ bias,
                          const float* __restrict__ x,
                          float* __restrict__ Cout, int M) {
  extern __shared__ char smem[];
  unsigned sbase = s2u(smem);
  int tid = threadIdx.x, lane = tid & 31, w = tid >> 5;
  int wm = (w & 3) * 32, wn = (w >> 2) * 32;
  int bx = blockIdx.x;
  int dest = (bx < 4) ? 0 : (bx < 8) ? 1 : 2;
  int cx = (bx < 4) ? bx : (bx < 8) ? bx - 4 : bx - 8;
  int rowBase = blockIdx.y * 128, colBase = cx * 64;
  const __nv_bfloat16* Bh = (dest == 0) ? g_wlh : (dest == 1) ? g_wrh : g_wsh;
  const __nv_bfloat16* Bl = (dest == 0) ? g_wll : (dest == 1) ? g_wrl : g_wsl;
  const float* biasv = (dest == 0) ? bl : (dest == 1) ? br : bias;

  float acc[2][4][4];
#pragma unroll
  for (int i = 0; i < 2; i++)
#pragma unroll
    for (int j = 0; j < 4; j++)
#pragma unroll
      for (int k = 0; k < 4; k++) acc[i][j][k] = 0.f;

  gemm_load(sbase, 0, 0, rowBase, colBase, Bh, Bl, M, tid);
  CP_COMMIT();
  CP_WAIT0();
  __syncthreads();
  gemm_load(sbase, 1, 64, rowBase, colBase, Bh, Bl, M, tid);
  CP_COMMIT();
  gemm_compute(sbase, 0, lane, wm, wn, acc);
  CP_WAIT0();
  __syncthreads();
  gemm_compute(sbase, 1, lane, wm, wn, acc);

  if (dest < 2) {
    int plane = colBase >> 7;
    __half* C = ((dest == 0) ? g_xl : g_xr) + (size_t)plane * NMAX * D;
    int colPlaneOff = colBase & 127;
#pragma unroll
    for (int mt = 0; mt < 2; mt++)
#pragma unroll
      for (int half = 0; half < 2; half++) {
        int row = rowBase + wm + mt * 16 + (lane >> 2) + half * 8;
        if (row >= M) continue;
#pragma unroll
        for (int nt = 0; nt < 4; nt++) {
          int coln = wn + nt * 8 + (lane & 3) * 2;
          float ox = acc[mt][nt][half * 2 + 0] + biasv[colBase + coln + 0];
          float oy = acc[mt][nt][half * 2 + 1] + biasv[colBase + coln + 1];
          *(__half2*)(C + (size_t)row * D + colPlaneOff + coln) =
              __floats2half2_rn(ox, oy);
        }
      }
  } else {
#pragma unroll
    for (int mt = 0; mt < 2; mt++)
#pragma unroll
      for (int half = 0; half < 2; half++) {
        int row = rowBase + wm + mt * 16 + (lane >> 2) + half * 8;
        if (row >= M) continue;
#pragma unroll
        for (int nt = 0; nt < 4; nt++) {
          int coln = wn + nt * 8 + (lane & 3) * 2;
          float2 o;
          o.x = acc[mt][nt][half * 2 + 0] + biasv[colBase + coln + 0];
          o.y = acc[mt][nt][half * 2 + 1] + biasv[colBase + coln + 1];
          float2 xv = *(const float2*)(x + (size_t)row * D + colBase + coln);
          o.x += xv.x;
          o.y += xv.y;
          *(float2*)(Cout + (size_t)row * D + colBase + coln) = o;
        }
      }
  }
}

// ---------------------------------------------------------------------------
// Fused edge pass: TWO warps per dst node (even/odd edge offsets), both heads,
// 2 edges per iteration per warp, smem combine of partials. No atomics.
// Block = 256 threads = 8 warps = 4 nodes.
// ---------------------------------------------------------------------------
__device__ __forceinline__ float lrelu(float v) { return v > 0.f ? v : 0.2f * v; }

__device__ __forceinline__ float dot_lrelu(float4 c, float4 r, float4 a) {
  return lrelu(c.x + r.x) * a.x + lrelu(c.y + r.y) * a.y +
         lrelu(c.z + r.z) * a.z + lrelu(c.w + r.w) * a.w;
}

__global__ __launch_bounds__(256)
void fused_edge_sp_kernel(const float* __restrict__ att,
                          float* __restrict__ out, int n) {
  __shared__ float s_att[256];
  __shared__ float4 s_acc[4][2][32];  // [node_local][head][lane]
  __shared__ float  s_z[4][2];
  s_att[threadIdx.x] = att[threadIdx.x];
  int w = threadIdx.x >> 5;
  int lane = threadIdx.x & 31;
  int nl = w >> 1;        // node local 0..3
  int h = w & 1;          // half (even/odd edge offsets)
  int node = blockIdx.x * 4 + nl;
  int deg = 0, beg = 0;
  if (node < n) {
    deg = g_deg[node];
    beg = g_off[node];
  }
  __syncthreads();

  const __half* xl0 = g_xl;
  const __half* xl1 = g_xl + (size_t)NMAX * D;

  float4 r0 = {0.f, 0.f, 0.f, 0.f}, r1 = {0.f, 0.f, 0.f, 0.f};
  if (node < n) {
    r0 = half4_to_float4(*(const uint2*)(g_xr + (size_t)node * D + lane * 4));
    r1 = half4_to_float4(
        *(const uint2*)(g_xr + (size_t)NMAX * D + (size_t)node * D + lane * 4));
  }
  float4 a0 = *(const float4*)&s_att[lane * 4];
  float4 a1 = *(const float4*)&s_att[128 + lane * 4];

  float4 acc0 = {0.f, 0.f, 0.f, 0.f}, acc1 = {0.f, 0.f, 0.f, 0.f};
  float z0 = 0.f, z1 = 0.f;

  // This warp handles edge offsets h, h+2, h+4, ... ; iterate in pairs
  // (k, k+2) with stride 4, prefetching the next pair.
  if (deg > h) {
    uint2 b00, b01, b10, b11;
    {
      size_t s0 = (size_t)g_srcs[beg + h] * D + lane * 4;
      size_t s1 = (size_t)g_srcs[beg + min(h + 2, deg - 1)] * D + lane * 4;
      b00 = *(const uint2*)(xl0 + s0);
      b01 = *(const uint2*)(xl1 + s0);
      b10 = *(const uint2*)(xl0 + s1);
      b11 = *(const uint2*)(xl1 + s1);
    }
    for (int k = h; k < deg; k += 4) {
      uint2 c00 = b00, c01 = b01, c10 = b10, c11 = b11;
      bool vb = (k + 2) < deg;
      if (k + 4 < deg) {
        size_t t0 = (size_t)g_srcs[beg + k + 4] * D + lane * 4;
        size_t t1 = (size_t)g_srcs[beg + min(k + 6, deg - 1)] * D + lane * 4;
        b00 = *(const uint2*)(xl0 + t0);
        b01 = *(const uint2*)(xl1 + t0);
        b10 = *(const uint2*)(xl0 + t1);
        b11 = *(const uint2*)(xl1 + t1);
      }
      float4 e00 = half4_to_float4(c00);
      float4 e01 = half4_to_float4(c01);
      float4 e10 = half4_to_float4(c10);
      float4 e11 = half4_to_float4(c11);
      float d0 = dot_lrelu(e00, r0, a0);
      float d1 = dot_lrelu(e01, r1, a1);
      float d2 = dot_lrelu(e10, r0, a0);
      float d3 = dot_lrelu(e11, r1, a1);
#pragma unroll
      for (int o = 16; o; o >>= 1) {
        d0 += __shfl_xor_sync(0xffffffffu, d0, o);
        d1 += __shfl_xor_sync(0xffffffffu, d1, o);
        d2 += __shfl_xor_sync(0xffffffffu, d2, o);
        d3 += __shfl_xor_sync(0xffffffffu, d3, o);
      }
      float w00 = __expf(d0);
      float w01 = __expf(d1);
      z0 += w00;
      z1 += w01;
      acc0.x = fmaf(w00, e00.x, acc0.x);
      acc0.y = fmaf(w00, e00.y, acc0.y);
      acc0.z = fmaf(w00, e00.z, acc0.z);
      acc0.w = fmaf(w00, e00.w, acc0.w);
      acc1.x = fmaf(w01, e01.x, acc1.x);
      acc1.y = fmaf(w01, e01.y, acc1.y);
      acc1.z = fmaf(w01, e01.z, acc1.z);
      acc1.w = fmaf(w01, e01.w, acc1.w);
      if (vb) {
        float w10 = __expf(d2);
        float w11 = __expf(d3);
        z0 += w10;
        z1 += w11;
        acc0.x = fmaf(w10, e10.x, acc0.x);
        acc0.y = fmaf(w10, e10.y, acc0.y);
        acc0.z = fmaf(w10, e10.z, acc0.z);
        acc0.w = fmaf(w10, e10.w, acc0.w);
        acc1.x = fmaf(w11, e11.x, acc1.x);
        acc1.y = fmaf(w11, e11.y, acc1.y);
        acc1.z = fmaf(w11, e11.z, acc1.z);
        acc1.w = fmaf(w11, e11.w, acc1.w);
      }
    }
  }

  // odd-half warps publish partials (zeros if inactive)
  if (h == 1) {
    s_acc[nl][0][lane] = acc0;
    s_acc[nl][1][lane] = acc1;
    if (lane == 0) {
      s_z[nl][0] = z0;
      s_z[nl][1] = z1;
    }
  }
  __syncthreads();

  if (h == 0 && node < n && deg > 0) {
    float4 p0 = s_acc[nl][0][lane];
    float4 p1 = s_acc[nl][1][lane];
    z0 += s_z[nl][0];
    z1 += s_z[nl][1];
    acc0.x += p0.x; acc0.y += p0.y; acc0.z += p0.z; acc0.w += p0.w;
    acc1.x += p1.x; acc1.y += p1.y; acc1.z += p1.z; acc1.w += p1.w;

    float v0 = 0.5f / (z0 + 1e-16f);
    float v1 = 0.5f / (z1 + 1e-16f);
    float* o = out + (size_t)node * D + lane * 4;
    float4 ov = *(float4*)o;
    ov.x += fmaf(v0, acc0.x, v1 * acc1.x);
    ov.y += fmaf(v0, acc0.y, v1 * acc1.y);
    ov.z += fmaf(v0, acc0.z, v1 * acc1.z);
    ov.w += fmaf(v0, acc0.w, v1 * acc1.w);
    *(float4*)o = ov;
  }
}

// ---------------------------------------------------------------------------
// Launch: fork-join streams (main: ln -> split -> gemm; side: CSR build)
// ---------------------------------------------------------------------------
extern "C" void kernel_launch(void* const* d_in, const int* in_sizes, int n_in,
                              void* d_out, int out_size) {
  const float* x     = (const float*)d_in[0];
  const int*   ei    = (const int*)d_in[1];
  const float* gamma = (const float*)d_in[2];
  const float* beta  = (const float*)d_in[3];
  const float* Wl    = (const float*)d_in[4];
  const float* bl    = (const float*)d_in[5];
  const float* Wr    = (const float*)d_in[6];
  const float* br    = (const float*)d_in[7];
  const float* att   = (const float*)d_in[8];
  const float* resW  = (const float*)d_in[9];
  const float* bias  = (const float*)d_in[10];
  int n = in_sizes[0] / D;
  int e = in_sizes[1] / 2;
  float* out = (float*)d_out;

  cudaFuncSetAttribute(hmma_gemm_all_kernel,
                       cudaFuncAttributeMaxDynamicSharedMemorySize, SM_TOTAL);

  int mt = (n + 127) / 128;
  int nb = (n + 1023) / 1024;

  cudaStream_t s1;
  cudaEvent_t evFork, evJoin;
  cudaStreamCreateWithFlags(&s1, cudaStreamNonBlocking);
  cudaEventCreateWithFlags(&evFork, cudaEventDisableTiming);
  cudaEventCreateWithFlags(&evJoin, cudaEventDisableTiming);

  cudaEventRecord(evFork, 0);
  cudaStreamWaitEvent(s1, evFork, 0);

  // main chain: LN+split -> weight splits -> all GEMMs
  ln_relu_kernel<<<(n * 32 + 255) / 256, 256>>>(x, gamma, beta, n);
  split_all_kernel<<<(81920 + 255) / 256, 256>>>(Wl, Wr, resW);
  hmma_gemm_all_kernel<<<dim3(10, mt), 256, SM_TOTAL>>>(bl, br, bias, x, out, n);

  // side chain: CSR build
  zero_deg_kernel<<<(n + 255) / 256, 256, 0, s1>>>(n);
  hist_kernel<<<(e + 255) / 256, 256, 0, s1>>>(ei, e);
  scan1_kernel<<<nb, 1024, 0, s1>>>(n);
  scan2_kernel<<<1, 128, 0, s1>>>(nb);
  scan3_kernel<<<(n + 255) / 256, 256, 0, s1>>>(n);
  scatter_kernel<<<(e + 255) / 256, 256, 0, s1>>>(ei, e);

  cudaEventRecord(evJoin, s1);
  cudaStreamWaitEvent(0, evJoin, 0);

  // edge pass: 2 warps per node, 4 nodes per block
  fused_edge_sp_kernel<<<(n + 3) / 4, 256>>>(att, out, n);

  cudaEventDestroy(evFork);
  cudaEventDestroy(evJoin);
  cudaStreamDestroy(s1);
}

// round 17
// speedup vs baseline: 1.1452x; 1.1452x over previous
#include <cuda_runtime.h>
#include <cuda_bf16.h>
#include <cuda_fp16.h>
#include <cstdint>
#include <math.h>

#define D 128
#define HD 256

static const int NMAX = 100000;
static const int EMAX = 1600000;

// ---------------------------------------------------------------------------
// Scratch. xl/xr stored as fp16 head-major planes [2][N][128].
// ---------------------------------------------------------------------------
__device__ __nv_bfloat16 g_hh[(size_t)NMAX * D];
__device__ __nv_bfloat16 g_hl[(size_t)NMAX * D];
__device__ __half g_xl [(size_t)2 * NMAX * D];
__device__ __half g_xr [(size_t)2 * NMAX * D];
__device__ __nv_bfloat16 g_wlh[HD * D];
__device__ __nv_bfloat16 g_wll[HD * D];
__device__ __nv_bfloat16 g_wrh[HD * D];
__device__ __nv_bfloat16 g_wrl[HD * D];
__device__ __nv_bfloat16 g_wsh[D * D];
__device__ __nv_bfloat16 g_wsl[D * D];
__device__ int   g_deg [NMAX];
__device__ int   g_off [NMAX];
__device__ int   g_pos [NMAX];
__device__ int   g_bsum[128];
__device__ int   g_srcs[EMAX];

// ---------------------------------------------------------------------------
// PTX helpers
// ---------------------------------------------------------------------------
__device__ __forceinline__ unsigned s2u(const void* p) {
  unsigned a;
  asm("{ .reg .u64 t; cvta.to.shared.u64 t, %1; cvt.u32.u64 %0, t; }"
      : "=r"(a) : "l"(p));
  return a;
}

__device__ __forceinline__ void ldm4(unsigned* r, unsigned addr) {
  asm volatile("ldmatrix.sync.aligned.m8n8.x4.shared.b16 {%0,%1,%2,%3}, [%4];"
               : "=r"(r[0]), "=r"(r[1]), "=r"(r[2]), "=r"(r[3]) : "r"(addr));
}

__device__ __forceinline__ void mma_bf16(float* c, const unsigned* a,
                                         const unsigned* b) {
  asm volatile(
      "mma.sync.aligned.m16n8k16.row.col.f32.bf16.bf16.f32 "
      "{%0,%1,%2,%3}, {%4,%5,%6,%7}, {%8,%9}, {%0,%1,%2,%3};"
      : "+f"(c[0]), "+f"(c[1]), "+f"(c[2]), "+f"(c[3])
      : "r"(a[0]), "r"(a[1]), "r"(a[2]), "r"(a[3]), "r"(b[0]), "r"(b[1]));
}

__device__ __forceinline__ void cpa16(unsigned daddr, const void* g) {
  asm volatile("cp.async.cg.shared.global [%0], [%1], 16;"
               :: "r"(daddr), "l"(g));
}
__device__ __forceinline__ void cpa8(unsigned daddr, const void* g) {
  asm volatile("cp.async.ca.shared.global [%0], [%1], 8;"
               :: "r"(daddr), "l"(g));
}
#define CP_COMMIT() asm volatile("cp.async.commit_group;" ::: "memory")
#define CP_WAIT0()  asm volatile("cp.async.wait_group 0;" ::: "memory")
#define CP_WAIT3()  asm volatile("cp.async.wait_group 3;" ::: "memory")

__device__ __forceinline__ uint2 pack_hi_lo(float4 v, uint2& lo) {
  __nv_bfloat162 h0 = __floats2bfloat162_rn(v.x, v.y);
  __nv_bfloat162 h1 = __floats2bfloat162_rn(v.z, v.w);
  float4 r;
  r.x = v.x - __bfloat162float(h0.x);
  r.y = v.y - __bfloat162float(h0.y);
  r.z = v.z - __bfloat162float(h1.x);
  r.w = v.w - __bfloat162float(h1.y);
  __nv_bfloat162 l0 = __floats2bfloat162_rn(r.x, r.y);
  __nv_bfloat162 l1 = __floats2bfloat162_rn(r.z, r.w);
  uint2 hi;
  hi.x = *(unsigned*)&h0;
  hi.y = *(unsigned*)&h1;
  lo.x = *(unsigned*)&l0;
  lo.y = *(unsigned*)&l1;
  return hi;
}

__device__ __forceinline__ float4 half4_to_float4(uint2 p) {
  float2 f01 = __half22float2(*(__half2*)&p.x);
  float2 f23 = __half22float2(*(__half2*)&p.y);
  float4 r;
  r.x = f01.x; r.y = f01.y; r.z = f23.x; r.w = f23.y;
  return r;
}

// ---------------------------------------------------------------------------
// LayerNorm + ReLU + bf16 split (warp per row)
// ---------------------------------------------------------------------------
__global__ void ln_relu_kernel(const float* __restrict__ x,
                               const float* __restrict__ gamma,
                               const float* __restrict__ beta, int n) {
  int gtid = blockIdx.x * blockDim.x + threadIdx.x;
  int row = gtid >> 5;
  int lane = gtid & 31;
  if (row >= n) return;

  float4 v = *(const float4*)(x + (size_t)row * D + lane * 4);
  float s = v.x + v.y + v.z + v.w;
#pragma unroll
  for (int o = 16; o; o >>= 1) s += __shfl_xor_sync(0xffffffffu, s, o);
  float mu = s * (1.f / 128.f);
  float dx = v.x - mu, dy = v.y - mu, dz = v.z - mu, dw = v.w - mu;
  float q = dx * dx + dy * dy + dz * dz + dw * dw;
#pragma unroll
  for (int o = 16; o; o >>= 1) q += __shfl_xor_sync(0xffffffffu, q, o);
  float rstd = rsqrtf(q * (1.f / 128.f) + 1e-5f);

  float4 g = *(const float4*)(gamma + lane * 4);
  float4 b = *(const float4*)(beta + lane * 4);
  float4 h;
  h.x = fmaxf(fmaf(dx * rstd, g.x, b.x), 0.f);
  h.y = fmaxf(fmaf(dy * rstd, g.y, b.y), 0.f);
  h.z = fmaxf(fmaf(dz * rstd, g.z, b.z), 0.f);
  h.w = fmaxf(fmaf(dw * rstd, g.w, b.w), 0.f);
  uint2 lo;
  uint2 hi = pack_hi_lo(h, lo);
  *(uint2*)(g_hh + (size_t)row * D + lane * 4) = hi;
  *(uint2*)(g_hl + (size_t)row * D + lane * 4) = lo;
}

// ---------------------------------------------------------------------------
// Merged weight transpose + bf16 split (Wl, Wr, resW in one launch)
// ---------------------------------------------------------------------------
__global__ void split_all_kernel(const float* __restrict__ Wl,
                                 const float* __restrict__ Wr,
                                 const float* __restrict__ Ws) {
  int i = blockIdx.x * blockDim.x + threadIdx.x;
  if (i >= 81920) return;
  const float* W;
  __nv_bfloat16 *oh, *ol;
  int rem, Ncols;
  if (i < 32768) {
    W = Wl; oh = g_wlh; ol = g_wll; rem = i; Ncols = HD;
  } else if (i < 65536) {
    W = Wr; oh = g_wrh; ol = g_wrl; rem = i - 32768; Ncols = HD;
  } else {
    W = Ws; oh = g_wsh; ol = g_wsl; rem = i - 65536; Ncols = D;
  }
  int nrow = rem >> 7;
  int k = rem & 127;
  float v = W[(size_t)k * Ncols + nrow];
  __nv_bfloat16 h = __float2bfloat16(v);
  __nv_bfloat16 l = __float2bfloat16(v - __bfloat162float(h));
  oh[rem] = h;
  ol[rem] = l;
}

// ---------------------------------------------------------------------------
// CSR build (independent side chain): zero -> hist -> scan -> scatter
// ---------------------------------------------------------------------------
__global__ void zero_deg_kernel(int n) {
  int i = blockIdx.x * blockDim.x + threadIdx.x;
  if (i < n) g_deg[i] = 0;
}

__global__ void hist_kernel(const int* __restrict__ ei, int e) {
  int i = blockIdx.x * blockDim.x + threadIdx.x;
  if (i < e) atomicAdd(&g_deg[ei[e + i]], 1);
}

__global__ __launch_bounds__(1024) void scan1_kernel(int n) {
  __shared__ int sh[1024];
  int i = blockIdx.x * 1024 + threadIdx.x;
  int v = (i < n) ? g_deg[i] : 0;
  sh[threadIdx.x] = v;
  __syncthreads();
#pragma unroll
  for (int o = 1; o < 1024; o <<= 1) {
    int t = (threadIdx.x >= o) ? sh[threadIdx.x - o] : 0;
    __syncthreads();
    sh[threadIdx.x] += t;
    __syncthreads();
  }
  int incl = sh[threadIdx.x];
  if (i < n) g_off[i] = incl - v;
  if (threadIdx.x == 1023) g_bsum[blockIdx.x] = incl;
}

__global__ void scan2_kernel(int nb) {
  __shared__ int sh[128];
  int i = threadIdx.x;
  int v = (i < nb) ? g_bsum[i] : 0;
  sh[i] = v;
  __syncthreads();
#pragma unroll
  for (int o = 1; o < 128; o <<= 1) {
    int t = (i >= o) ? sh[i - o] : 0;
    __syncthreads();
    sh[i] += t;
    __syncthreads();
  }
  if (i < nb) g_bsum[i] = sh[i] - v;
}

__global__ void scan3_kernel(int n) {
  int i = blockIdx.x * blockDim.x + threadIdx.x;
  if (i < n) {
    int o = g_off[i] + g_bsum[i >> 10];
    g_off[i] = o;
    g_pos[i] = o;
  }
}

__global__ void scatter_kernel(const int* __restrict__ ei, int e) {
  int i = blockIdx.x * blockDim.x + threadIdx.x;
  if (i < e) {
    int dst = ei[e + i];
    int p = atomicAdd(&g_pos[dst], 1);
    g_srcs[p] = ei[i];
  }
}

// ---------------------------------------------------------------------------
// MERGED bf16x3 GEMM: blockIdx.x 0-3 -> xl, 4-7 -> xr, 8-9 -> out.
// ---------------------------------------------------------------------------
#define BPAD 72
#define OFF_AH 0
#define OFF_AL (128 * BPAD)
#define OFF_BH (256 * BPAD)
#define OFF_BL (320 * BPAD)
#define BUF_HALVES (384 * BPAD)
#define SM_TOTAL (2 * BUF_HALVES * 2)

__device__ __forceinline__ void gemm_load(unsigned sbase, int buf,
                                          int kc, int rowBase, int colBase,
                                          const __nv_bfloat16* Bh,
                                          const __nv_bfloat16* Bl,
                                          int M, int tid) {
  unsigned base = sbase + buf * BUF_HALVES * 2;
  for (int idx = tid; idx < 1024; idx += 256) {
    int row = idx >> 3, c = idx & 7;
    int rg = min(rowBase + row, M - 1);
    unsigned so = (row * BPAD + c * 8) * 2;
    cpa16(base + OFF_AH * 2 + so, g_hh + (size_t)rg * D + kc + c * 8);
    cpa16(base + OFF_AL * 2 + so, g_hl + (size_t)rg * D + kc + c * 8);
  }
  for (int idx = tid; idx < 512; idx += 256) {
    int row = idx >> 3, c = idx & 7;
    unsigned so = (row * BPAD + c * 8) * 2;
    cpa16(base + OFF_BH * 2 + so, Bh + (size_t)(colBase + row) * D + kc + c * 8);
    cpa16(base + OFF_BL * 2 + so, Bl + (size_t)(colBase + row) * D + kc + c * 8);
  }
}

__device__ __forceinline__ void gemm_compute(unsigned sbase, int buf, int lane,
                                             int wm, int wn,
                                             float acc[2][4][4]) {
  unsigned base = sbase + buf * BUF_HALVES * 2;
#pragma unroll
  for (int ks = 0; ks < 4; ks++) {
    unsigned aH[2][4], aL[2][4], bH[2][4], bL[2][4];
    unsigned aoff = ((wm + (lane & 15)) * BPAD + ks * 16 + (lane >> 4) * 8) * 2;
    unsigned boff = ((wn + (lane & 7) + ((lane >> 4) << 3)) * BPAD +
                     ks * 16 + (((lane >> 3) & 1) << 3)) * 2;
#pragma unroll
    for (int mt = 0; mt < 2; mt++) {
      ldm4(aH[mt], base + OFF_AH * 2 + aoff + mt * (16 * BPAD * 2));
      ldm4(aL[mt], base + OFF_AL * 2 + aoff + mt * (16 * BPAD * 2));
    }
#pragma unroll
    for (int j = 0; j < 2; j++) {
      ldm4(bH[j], base + OFF_BH * 2 + boff + j * (16 * BPAD * 2));
      ldm4(bL[j], base + OFF_BL * 2 + boff + j * (16 * BPAD * 2));
    }
#pragma unroll
    for (int mt = 0; mt < 2; mt++)
#pragma unroll
      for (int j = 0; j < 2; j++) {
        mma_bf16(acc[mt][2 * j + 0], aH[mt], &bH[j][0]);
        mma_bf16(acc[mt][2 * j + 1], aH[mt], &bH[j][2]);
        mma_bf16(acc[mt][2 * j + 0], aH[mt], &bL[j][0]);
        mma_bf16(acc[mt][2 * j + 1], aH[mt], &bL[j][2]);
        mma_bf16(acc[mt][2 * j + 0], aL[mt], &bH[j][0]);
        mma_bf16(acc[mt][2 * j + 1], aL[mt], &bH[j][2]);
      }
  }
}

__global__ __launch_bounds__(256, 2)
void hmma_gemm_all_kernel(const float* __restrict__ bl,
                          const float* __restrict__ br,
                          const float* __restrict__ bias,
                          const float* __restrict__ x,
                          float* __restrict__ Cout, int M) {
  extern __shared__ char smem[];
  unsigned sbase = s2u(smem);
  int tid = threadIdx.x, lane = tid & 31, w = tid >> 5;
  int wm = (w & 3) * 32, wn = (w >> 2) * 32;
  int bx = blockIdx.x;
  int dest = (bx < 4) ? 0 : (bx < 8) ? 1 : 2;
  int cx = (bx < 4) ? bx : (bx < 8) ? bx - 4 : bx - 8;
  int rowBase = blockIdx.y * 128, colBase = cx * 64;
  const __nv_bfloat16* Bh = (dest == 0) ? g_wlh : (dest == 1) ? g_wrh : g_wsh;
  const __nv_bfloat16* Bl = (dest == 0) ? g_wll : (dest == 1) ? g_wrl : g_wsl;
  const float* biasv = (dest == 0) ? bl : (dest == 1) ? br : bias;

  float acc[2][4][4];
#pragma unroll
  for (int i = 0; i < 2; i++)
#pragma unroll
    for (int j = 0; j < 4; j++)
#pragma unroll
      for (int k = 0; k < 4; k++) acc[i][j][k] = 0.f;

  gemm_load(sbase, 0, 0, rowBase, colBase, Bh, Bl, M, tid);
  CP_COMMIT();
  CP_WAIT0();
  __syncthreads();
  gemm_load(sbase, 1, 64, rowBase, colBase, Bh, Bl, M, tid);
  CP_COMMIT();
  gemm_compute(sbase, 0, lane, wm, wn, acc);
  CP_WAIT0();
  __syncthreads();
  gemm_compute(sbase, 1, lane, wm, wn, acc);

  if (dest < 2) {
    int plane = colBase >> 7;
    __half* C = ((dest == 0) ? g_xl : g_xr) + (size_t)plane * NMAX * D;
    int colPlaneOff = colBase & 127;
#pragma unroll
    for (int mt = 0; mt < 2; mt++)
#pragma unroll
      for (int half = 0; half < 2; half++) {
        int row = rowBase + wm + mt * 16 + (lane >> 2) + half * 8;
        if (row >= M) continue;
#pragma unroll
        for (int nt = 0; nt < 4; nt++) {
          int coln = wn + nt * 8 + (lane & 3) * 2;
          float ox = acc[mt][nt][half * 2 + 0] + biasv[colBase + coln + 0];
          float oy = acc[mt][nt][half * 2 + 1] + biasv[colBase + coln + 1];
          *(__half2*)(C + (size_t)row * D + colPlaneOff + coln) =
              __floats2half2_rn(ox, oy);
        }
      }
  } else {
#pragma unroll
    for (int mt = 0; mt < 2; mt++)
#pragma unroll
      for (int half = 0; half < 2; half++) {
        int row = rowBase + wm + mt * 16 + (lane >> 2) + half * 8;
        if (row >= M) continue;
#pragma unroll
        for (int nt = 0; nt < 4; nt++) {
          int coln = wn + nt * 8 + (lane & 3) * 2;
          float2 o;
          o.x = acc[mt][nt][half * 2 + 0] + biasv[colBase + coln + 0];
          o.y = acc[mt][nt][half * 2 + 1] + biasv[colBase + coln + 1];
          float2 xv = *(const float2*)(x + (size_t)row * D + colBase + coln);
          o.x += xv.x;
          o.y += xv.y;
          *(float2*)(Cout + (size_t)row * D + colBase + coln) = o;
        }
      }
  }
}

// ---------------------------------------------------------------------------
// Fused edge pass: warp per dst node, both heads, 2 edges per iteration,
// cp.async 4-stage smem ring (8 edges in flight; no prefetch registers).
// Block = 256 threads = 8 warps = 8 nodes.
// ---------------------------------------------------------------------------
__device__ __forceinline__ float lrelu(float v) { return v > 0.f ? v : 0.2f * v; }

__device__ __forceinline__ float dot_lrelu(float4 c, float4 r, float4 a) {
  return lrelu(c.x + r.x) * a.x + lrelu(c.y + r.y) * a.y +
         lrelu(c.z + r.z) * a.z + lrelu(c.w + r.w) * a.w;
}

__global__ __launch_bounds__(256)
void fused_edge_ring_kernel(const float* __restrict__ att,
                            float* __restrict__ out, int n) {
  __shared__ float s_att[256];
  __shared__ uint2 s_ring[8][4][4][32];  // [warp][stage][slot][lane]
  s_att[threadIdx.x] = att[threadIdx.x];
  __syncthreads();
  int w = threadIdx.x >> 5;
  int lane = threadIdx.x & 31;
  int node = blockIdx.x * 8 + w;
  if (node >= n) return;
  int deg = g_deg[node];
  if (deg == 0) return;
  int beg = g_off[node];

  const __half* xl0 = g_xl;
  const __half* xl1 = g_xl + (size_t)NMAX * D;

  float4 r0 = half4_to_float4(*(const uint2*)(g_xr + (size_t)node * D + lane * 4));
  float4 r1 = half4_to_float4(
      *(const uint2*)(g_xr + (size_t)NMAX * D + (size_t)node * D + lane * 4));
  float4 a0 = *(const float4*)&s_att[lane * 4];
  float4 a1 = *(const float4*)&s_att[128 + lane * 4];

  float4 acc0 = {0.f, 0.f, 0.f, 0.f}, acc1 = {0.f, 0.f, 0.f, 0.f};
  float z0 = 0.f, z1 = 0.f;

  int npairs = (deg + 1) >> 1;

  // issue one pair (2 edges x 2 planes, 8B per lane) into ring stage p&3
#define ISSUE_PAIR(p)                                                       \
  do {                                                                      \
    int st_ = (p) & 3;                                                      \
    int k_ = (p) * 2;                                                       \
    int i0_ = min(k_, deg - 1);                                             \
    int i1_ = min(k_ + 1, deg - 1);                                         \
    size_t s0_ = (size_t)g_srcs[beg + i0_] * D + lane * 4;                  \
    size_t s1_ = (size_t)g_srcs[beg + i1_] * D + lane * 4;                  \
    cpa8(s2u(&s_ring[w][st_][0][lane]), xl0 + s0_);                         \
    cpa8(s2u(&s_ring[w][st_][1][lane]), xl1 + s0_);                         \
    cpa8(s2u(&s_ring[w][st_][2][lane]), xl0 + s1_);                         \
    cpa8(s2u(&s_ring[w][st_][3][lane]), xl1 + s1_);                         \
    CP_COMMIT();                                                            \
  } while (0)

  ISSUE_PAIR(0);
  ISSUE_PAIR(1);
  ISSUE_PAIR(2);

  for (int p = 0; p < npairs; p++) {
    ISSUE_PAIR(p + 3);
    CP_WAIT3();
    int st = p & 3;
    float4 e00 = half4_to_float4(s_ring[w][st][0][lane]);
    float4 e01 = half4_to_float4(s_ring[w][st][1][lane]);
    float4 e10 = half4_to_float4(s_ring[w][st][2][lane]);
    float4 e11 = half4_to_float4(s_ring[w][st][3][lane]);
    float d0 = dot_lrelu(e00, r0, a0);
    float d1 = dot_lrelu(e01, r1, a1);
    float d2 = dot_lrelu(e10, r0, a0);
    float d3 = dot_lrelu(e11, r1, a1);
#pragma unroll
    for (int o = 16; o; o >>= 1) {
      d0 += __shfl_xor_sync(0xffffffffu, d0, o);
      d1 += __shfl_xor_sync(0xffffffffu, d1, o);
      d2 += __shfl_xor_sync(0xffffffffu, d2, o);
      d3 += __shfl_xor_sync(0xffffffffu, d3, o);
    }
    float w00 = __expf(d0);
    float w01 = __expf(d1);
    z0 += w00;
    z1 += w01;
    acc0.x = fmaf(w00, e00.x, acc0.x);
    acc0.y = fmaf(w00, e00.y, acc0.y);
    acc0.z = fmaf(w00, e00.z, acc0.z);
    acc0.w = fmaf(w00, e00.w, acc0.w);
    acc1.x = fmaf(w01, e01.x, acc1.x);
    acc1.y = fmaf(w01, e01.y, acc1.y);
    acc1.z = fmaf(w01, e01.z, acc1.z);
    acc1.w = fmaf(w01, e01.w, acc1.w);
    if (p * 2 + 1 < deg) {
      float w10 = __expf(d2);
      float w11 = __expf(d3);
      z0 += w10;
      z1 += w11;
      acc0.x = fmaf(w10, e10.x, acc0.x);
      acc0.y = fmaf(w10, e10.y, acc0.y);
      acc0.z = fmaf(w10, e10.z, acc0.z);
      acc0.w = fmaf(w10, e10.w, acc0.w);
      acc1.x = fmaf(w11, e11.x, acc1.x);
      acc1.y = fmaf(w11, e11.y, acc1.y);
      acc1.z = fmaf(w11, e11.z, acc1.z);
      acc1.w = fmaf(w11, e11.w, acc1.w);
    }
  }
  CP_WAIT0();
#undef ISSUE_PAIR

  float v0 = 0.5f / (z0 + 1e-16f);
  float v1 = 0.5f / (z1 + 1e-16f);
  float* o = out + (size_t)node * D + lane * 4;
  float4 ov = *(float4*)o;
  ov.x += fmaf(v0, acc0.x, v1 * acc1.x);
  ov.y += fmaf(v0, acc0.y, v1 * acc1.y);
  ov.z += fmaf(v0, acc0.z, v1 * acc1.z);
  ov.w += fmaf(v0, acc0.w, v1 * acc1.w);
  *(float4*)o = ov;
}

// ---------------------------------------------------------------------------
// Launch: fork-join streams (main: ln -> split -> gemm; side: CSR build)
// ---------------------------------------------------------------------------
extern "C" void kernel_launch(void* const* d_in, const int* in_sizes, int n_in,
                              void* d_out, int out_size) {
  const float* x     = (const float*)d_in[0];
  const int*   ei    = (const int*)d_in[1];
  const float* gamma = (const float*)d_in[2];
  const float* beta  = (const float*)d_in[3];
  const float* Wl    = (const float*)d_in[4];
  const float* bl    = (const float*)d_in[5];
  const float* Wr    = (const float*)d_in[6];
  const float* br    = (const float*)d_in[7];
  const float* att   = (const float*)d_in[8];
  const float* resW  = (const float*)d_in[9];
  const float* bias  = (const float*)d_in[10];
  int n = in_sizes[0] / D;
  int e = in_sizes[1] / 2;
  float* out = (float*)d_out;

  cudaFuncSetAttribute(hmma_gemm_all_kernel,
                       cudaFuncAttributeMaxDynamicSharedMemorySize, SM_TOTAL);

  int mt = (n + 127) / 128;
  int nb = (n + 1023) / 1024;

  cudaStream_t s1;
  cudaEvent_t evFork, evJoin;
  cudaStreamCreateWithFlags(&s1, cudaStreamNonBlocking);
  cudaEventCreateWithFlags(&evFork, cudaEventDisableTiming);
  cudaEventCreateWithFlags(&evJoin, cudaEventDisableTiming);

  cudaEventRecord(evFork, 0);
  cudaStreamWaitEvent(s1, evFork, 0);

  // main chain: LN+split -> weight splits -> all GEMMs
  ln_relu_kernel<<<(n * 32 + 255) / 256, 256>>>(x, gamma, beta, n);
  split_all_kernel<<<(81920 + 255) / 256, 256>>>(Wl, Wr, resW);
  hmma_gemm_all_kernel<<<dim3(10, mt), 256, SM_TOTAL>>>(bl, br, bias, x, out, n);

  // side chain: CSR build
  zero_deg_kernel<<<(n + 255) / 256, 256, 0, s1>>>(n);
  hist_kernel<<<(e + 255) / 256, 256, 0, s1>>>(ei, e);
  scan1_kernel<<<nb, 1024, 0, s1>>>(n);
  scan2_kernel<<<1, 128, 0, s1>>>(nb);
  scan3_kernel<<<(n + 255) / 256, 256, 0, s1>>>(n);
  scatter_kernel<<<(e + 255) / 256, 256, 0, s1>>>(ei, e);

  cudaEventRecord(evJoin, s1);
  cudaStreamWaitEvent(0, evJoin, 0);

  fused_edge_ring_kernel<<<(n + 7) / 8, 256>>>(att, out, n);

  cudaEventDestroy(evFork);
  cudaEventDestroy(evJoin);
  cudaStreamDestroy(s1);
}